// round 10
// baseline (speedup 1.0000x reference)
#include <cuda_runtime.h>
#include <math.h>

#define DD 96
#define NPART 48
#define PITCH 97
#define NB 8

__device__ double g_G[DD * DD];
__device__ double g_pk[NPART];

// Fast fp64 reciprocal: f32 rcp seed + 2 fp64 Newton steps (~1e-14 rel).
__device__ __forceinline__ double fast_recip(double p) {
    float pf = (float)p;
    float rf;
    asm("rcp.approx.f32 %0, %1;" : "=f"(rf) : "f"(pf));
    double r = (double)rf;
    r = r * __fma_rn(-p, r, 2.0);
    r = r * __fma_rn(-p, r, 2.0);
    return r;
}

// ---------------------------------------------------------------------------
// G = I - P P^T (upper triangle is what the LU consumes; compute full, cheap).
// ---------------------------------------------------------------------------
__global__ void build_G_kernel(const float* __restrict__ P) {
    __shared__ float Pt[NPART][DD];  // Pt[t][i] = P[i*NPART+t]
    const int i = blockIdx.x;
    const int tid = threadIdx.x;  // 96

    for (int idx = tid; idx < DD * NPART; idx += DD) {
        int r = idx / NPART;
        int t = idx - r * NPART;
        Pt[t][r] = P[idx];
    }
    __syncthreads();

    const int j = tid;
    double a0 = 0.0, a1 = 0.0, a2 = 0.0, a3 = 0.0;
#pragma unroll
    for (int t = 0; t < NPART; t += 4) {
        a0 = __fma_rn((double)Pt[t][i],     (double)Pt[t][j],     a0);
        a1 = __fma_rn((double)Pt[t + 1][i], (double)Pt[t + 1][j], a1);
        a2 = __fma_rn((double)Pt[t + 2][i], (double)Pt[t + 2][j], a2);
        a3 = __fma_rn((double)Pt[t + 3][i], (double)Pt[t + 3][j], a3);
    }
    g_G[i * DD + j] = ((i == j) ? 1.0 : 0.0) - ((a0 + a1) + (a2 + a3));
}

// ---------------------------------------------------------------------------
// Blocked (NB=8) unpivoted symmetric elimination on the UPPER triangle of the
// leading m x m block (m = 49+k).  Per panel:
//   (1) every thread redundantly factors the 8x8 diagonal block in registers
//       (no barriers; gives all L[s][t] and inv_t locally),
//   (2) updates the 8 pivot rows for its 3 owned columns in registers, stores,
//   (3) rank-8 trailing update: 1 LDS + 8 reg-FMA + 1 STS per element.
// 2 barriers per panel (24 total).
// ---------------------------------------------------------------------------
__global__ void __launch_bounds__(256, 1)
lu_probs_kernel(const int* __restrict__ occ, float* __restrict__ out) {
    extern __shared__ double A_[];   // [DD][PITCH]
    __shared__ double s_piv[DD];
    __shared__ double sc[2][DD];
    __shared__ int s_occ[NPART];

    const int k = blockIdx.x;
    const int m = DD - NPART + k + 1;   // 49 + k
    const int tid = threadIdx.x;        // 256
    const int tx = tid & 31;
    const int ty = tid >> 5;

    if (tid < NPART) s_occ[tid] = occ[tid];

    const int c0 = tx, c1 = tx + 32, c2 = tx + 64;

    // Load upper triangle of the leading m x m block of G.
    for (int r = ty; r < m; r += 8) {
        double* __restrict__ arow = &A_[r * PITCH];
        if (c0 >= r)           arow[c0] = g_G[r * DD + c0];
        if (c1 >= r && c1 < m) arow[c1] = g_G[r * DD + c1];
        if (c2 >= r && c2 < m) arow[c2] = g_G[r * DD + c2];
    }
    __syncthreads();
    if (tid < k) {                      // distinct positions -> race-free
        int p = s_occ[tid];
        if (p < m) A_[p * PITCH + p] -= 1.0;
    }
    __syncthreads();

    for (int i0 = 0; i0 < m; i0 += NB) {
        const int w = min(NB, m - i0);

        // ---- (1) redundant 8x8 upper-block factorization in registers ----
        double Db[NB][NB];
        double inv[NB];
#pragma unroll
        for (int s = 0; s < NB; s++)
#pragma unroll
            for (int t = s; t < NB; t++)
                Db[s][t] = (t < w) ? A_[(i0 + s) * PITCH + (i0 + t)]
                                   : ((s == t) ? 1.0 : 0.0);
        inv[0] = fast_recip(Db[0][0]);
#pragma unroll
        for (int t = 1; t < NB; t++) {
#pragma unroll
            for (int s = 0; s < t; s++) {
                const double l = Db[s][t] * inv[s];
#pragma unroll
                for (int c = t; c < NB; c++)
                    Db[t][c] = __fma_rn(-l, Db[s][c], Db[t][c]);
            }
            inv[t] = fast_recip(Db[t][t]);
        }
        if (tid == 0) {
#pragma unroll
            for (int t = 0; t < NB; t++)
                if (t < w) s_piv[i0 + t] = Db[t][t];
        }

        // ---- (2) update pivot rows for owned columns, in registers ----
        double U0[NB], U1[NB], U2[NB];
#pragma unroll
        for (int t = 0; t < NB; t++) {
            const int rt = i0 + t;
            U0[t] = (t < w && c0 >= rt)            ? A_[rt * PITCH + c0] : 0.0;
            U1[t] = (t < w && c1 >= rt && c1 < m)  ? A_[rt * PITCH + c1] : 0.0;
            U2[t] = (t < w && c2 >= rt && c2 < m)  ? A_[rt * PITCH + c2] : 0.0;
        }
#pragma unroll
        for (int t = 1; t < NB; t++)
#pragma unroll
            for (int s = 0; s < t; s++) {
                const double l = Db[s][t] * inv[s];
                U0[t] = __fma_rn(-l, U0[s], U0[t]);
                U1[t] = __fma_rn(-l, U1[s], U1[t]);
                U2[t] = __fma_rn(-l, U2[s], U2[t]);
            }
#pragma unroll
        for (int t = 0; t < NB; t++) {
            const int rt = i0 + t;
            if (t < w) {
                if (c0 >= rt)           A_[rt * PITCH + c0] = U0[t];
                if (c1 >= rt && c1 < m) A_[rt * PITCH + c1] = U1[t];
                if (c2 >= rt && c2 < m) A_[rt * PITCH + c2] = U2[t];
            }
        }
        __syncthreads();

        // ---- (3) rank-8 trailing update (upper triangle) ----
        const int rbase = i0 + w;
        if (rbase < m) {
            for (int r = rbase + ((ty - rbase) & 7); r < m; r += 8) {
                double l[NB];
#pragma unroll
                for (int t = 0; t < NB; t++)
                    l[t] = (t < w) ? A_[(i0 + t) * PITCH + r] * inv[t] : 0.0;
                double* __restrict__ arow = &A_[r * PITCH];
                if (r <= 31) {                   // block j=0, warp-uniform
                    if (c0 >= r) {
                        double v = arow[c0];
#pragma unroll
                        for (int t = 0; t < NB; t++) v = __fma_rn(-l[t], U0[t], v);
                        arow[c0] = v;
                    }
                }
                if (r <= 63) {                   // block j=1
                    if (c1 >= r && c1 < m) {
                        double v = arow[c1];
#pragma unroll
                        for (int t = 0; t < NB; t++) v = __fma_rn(-l[t], U1[t], v);
                        arow[c1] = v;
                    }
                }
                {                                 // block j=2
                    if (c2 >= r && c2 < m) {
                        double v = arow[c2];
#pragma unroll
                        for (int t = 0; t < NB; t++) v = __fma_rn(-l[t], U2[t], v);
                        arow[c2] = v;
                    }
                }
            }
        }
        __syncthreads();
    }

    const int xmin = (k == 0) ? 0 : s_occ[k - 1] + 1;

    // Inclusive prefix product of pivots masked to [xmin, m).
    if (tid < DD) sc[0][tid] = (tid >= xmin && tid < m) ? s_piv[tid] : 1.0;
    __syncthreads();
    int src = 0;
    for (int off = 1; off < DD; off <<= 1) {
        if (tid < DD) {
            double v = sc[src][tid];
            if (tid >= off) v *= sc[src][tid - off];
            sc[src ^ 1][tid] = v;
        }
        __syncthreads();
        src ^= 1;
    }

    if (tid < DD) {
        const int x = tid;
        double pr = 0.0;
        if (x >= xmin && x < m) {
            const double S = (x == xmin) ? 1.0 : sc[src][x - 1];
            pr = -S * (s_piv[x] - 1.0);
            if (!(fabs(pr) > 1e-15)) pr = 0.0;
        }
        out[k * DD + x] = (float)pr;
        if (x == s_occ[k]) g_pk[k] = pr;
    }
}

// ---------------------------------------------------------------------------
// prob_sample = prod_k p_k.
// ---------------------------------------------------------------------------
__global__ void prod_kernel(float* __restrict__ out) {
    const int t = threadIdx.x;  // 32
    double v = g_pk[t];
    if (t < 16) v *= g_pk[32 + t];
#pragma unroll
    for (int off = 16; off > 0; off >>= 1)
        v *= __shfl_xor_sync(0xFFFFFFFFu, v, off);
    if (t == 0) out[NPART * DD] = (float)v;
}

extern "C" void kernel_launch(void* const* d_in, const int* in_sizes, int n_in,
                              void* d_out, int out_size) {
    const float* P;
    const int* occ;
    if (in_sizes[0] == DD * NPART) {
        P = (const float*)d_in[0];
        occ = (const int*)d_in[1];
    } else {
        P = (const float*)d_in[1];
        occ = (const int*)d_in[0];
    }
    float* out = (float*)d_out;

    const int smem = DD * PITCH * (int)sizeof(double);  // 74496 B
    cudaFuncSetAttribute(lu_probs_kernel,
                         cudaFuncAttributeMaxDynamicSharedMemorySize, smem);

    build_G_kernel<<<DD, DD>>>(P);
    lu_probs_kernel<<<NPART, 256, smem>>>(occ, out);
    prod_kernel<<<1, 32>>>(out);
}

// round 13
// speedup vs baseline: 1.5636x; 1.5636x over previous
#include <cuda_runtime.h>
#include <math.h>

#define DD 96
#define NPART 48
#define PITCH 97

__device__ double g_G[DD * DD];
__device__ double g_pk[NPART];

// Fast fp64 reciprocal: f32 rcp seed + 2 fp64 Newton steps (~1e-14 rel).
__device__ __forceinline__ double fast_recip(double p) {
    float pf = (float)p;
    float rf;
    asm("rcp.approx.f32 %0, %1;" : "=f"(rf) : "f"(pf));
    double r = (double)rf;
    r = r * __fma_rn(-p, r, 2.0);
    r = r * __fma_rn(-p, r, 2.0);
    return r;
}

// ---------------------------------------------------------------------------
// G = I - P P^T  (96 blocks x 96 threads; measured-best variant).
// ---------------------------------------------------------------------------
__global__ void build_G_kernel(const float* __restrict__ P) {
    __shared__ float Pt[NPART][DD];  // Pt[t][i] = P[i*NPART+t]
    const int i = blockIdx.x;
    const int tid = threadIdx.x;  // 96

    for (int idx = tid; idx < DD * NPART; idx += DD) {
        int r = idx / NPART;
        int t = idx - r * NPART;
        Pt[t][r] = P[idx];
    }
    __syncthreads();

    const int j = tid;
    double a0 = 0.0, a1 = 0.0, a2 = 0.0, a3 = 0.0;
#pragma unroll
    for (int t = 0; t < NPART; t += 4) {
        a0 = __fma_rn((double)Pt[t][i],     (double)Pt[t][j],     a0);
        a1 = __fma_rn((double)Pt[t + 1][i], (double)Pt[t + 1][j], a1);
        a2 = __fma_rn((double)Pt[t + 2][i], (double)Pt[t + 2][j], a2);
        a3 = __fma_rn((double)Pt[t + 3][i], (double)Pt[t + 3][j], a3);
    }
    g_G[i * DD + j] = ((i == j) ? 1.0 : 0.0) - ((a0 + a1) + (a2 + a3));
}

// ---------------------------------------------------------------------------
// Per-k unpivoted symmetric elimination of the leading m x m block (m = 49+k).
// r2's memory pattern, but:
//  - pivot row lives in a DEDICATED double-buffered shared array ubuf[2][DD]
//    (distinct symbol from A_ -> no aliasing -> the update loop pipelines),
//  - factors l_r = ubuf[r]*inv (symmetry of the iterate),
//  - the warp owning row i+1 publishes it into the other ubuf slot and its
//    lane 0 captures the pivot in-register + computes fast_recip,
//  - ONE __syncthreads per step.
// ---------------------------------------------------------------------------
__global__ void __launch_bounds__(256, 1)
lu_probs_kernel(const int* __restrict__ occ, float* __restrict__ out) {
    extern __shared__ double A_[];     // [DD][PITCH] dynamic
    __shared__ double ubuf[2][DD];     // double-buffered pivot row
    __shared__ double s_piv[DD];
    __shared__ double s_inv[2];
    __shared__ double sc[2][DD];
    __shared__ int s_occ[NPART];

    const int k = blockIdx.x;
    const int m = DD - NPART + k + 1;   // 49 + k
    const int tid = threadIdx.x;        // 256
    const int tx = tid & 31;
    const int ty = tid >> 5;

    if (tid < NPART) s_occ[tid] = occ[tid];

    // Load leading m x m block of G (full rectangle; trailing block is dense).
    for (int r = ty; r < m; r += 8)
        for (int c = tx; c < m; c += 32)
            A_[r * PITCH + c] = g_G[r * DD + c];
    __syncthreads();
    if (tid < k) {                      // distinct positions -> race-free
        int p = s_occ[tid];
        if (p < m) A_[p * PITCH + p] -= 1.0;
    }
    __syncthreads();

    // Init: row 0 -> ubuf[0]; pivot 0 + reciprocal.
    if (tid < m) ubuf[0][tid] = A_[tid];
    if (tid == 0) {
        double p0 = A_[0];
        s_piv[0] = p0;
        s_inv[0] = fast_recip(p0);
    }
    __syncthreads();

    const int mstop = m - 1;
    for (int i = 0; i < mstop; i++) {
        const int par = i & 1;
        const double inv = s_inv[par];
        const double* __restrict__ ub = ubuf[par];
        double* __restrict__ un = ubuf[par ^ 1];
        const int ip1 = i + 1;

        // Rows r ≡ ty (mod 8), r >= i+1, ascending (owner warp hits i+1 first).
        int r = ip1 + ((ty - ip1) & 7);
        if (r == ip1) {
            // Publish row i+1 while updating it; capture pivot at c == i+1.
            const double l = ub[r] * inv;
            double* __restrict__ arow = &A_[r * PITCH];
            double pcap = 0.0;
            for (int c = ip1 + tx; c < m; c += 32) {
                double v = __fma_rn(-l, ub[c], arow[c]);
                arow[c] = v;
                un[c] = v;
                if (c == ip1) pcap = v;     // only tx==0, first iteration
            }
            if (tx == 0) {
                s_piv[ip1] = pcap;
                s_inv[par ^ 1] = fast_recip(pcap);
            }
            r += 8;
        }
        for (; r < m; r += 8) {
            const double l = ub[r] * inv;
            double* __restrict__ arow = &A_[r * PITCH];
            for (int c = ip1 + tx; c < m; c += 32)
                arow[c] = __fma_rn(-l, ub[c], arow[c]);
        }
        __syncthreads();
    }

    const int xmin = (k == 0) ? 0 : s_occ[k - 1] + 1;

    // Inclusive prefix product of pivots masked to [xmin, m).
    if (tid < DD) sc[0][tid] = (tid >= xmin && tid < m) ? s_piv[tid] : 1.0;
    __syncthreads();
    int src = 0;
    for (int off = 1; off < DD; off <<= 1) {
        if (tid < DD) {
            double v = sc[src][tid];
            if (tid >= off) v *= sc[src][tid - off];
            sc[src ^ 1][tid] = v;
        }
        __syncthreads();
        src ^= 1;
    }

    if (tid < DD) {
        const int x = tid;
        double pr = 0.0;
        if (x >= xmin && x < m) {
            const double S = (x == xmin) ? 1.0 : sc[src][x - 1];
            pr = -S * (s_piv[x] - 1.0);
            if (!(fabs(pr) > 1e-15)) pr = 0.0;
        }
        out[k * DD + x] = (float)pr;
        if (x == s_occ[k]) g_pk[k] = pr;
    }
}

// ---------------------------------------------------------------------------
// prob_sample = prod_k p_k.
// ---------------------------------------------------------------------------
__global__ void prod_kernel(float* __restrict__ out) {
    const int t = threadIdx.x;  // 32
    double v = g_pk[t];
    if (t < 16) v *= g_pk[32 + t];
#pragma unroll
    for (int off = 16; off > 0; off >>= 1)
        v *= __shfl_xor_sync(0xFFFFFFFFu, v, off);
    if (t == 0) out[NPART * DD] = (float)v;
}

extern "C" void kernel_launch(void* const* d_in, const int* in_sizes, int n_in,
                              void* d_out, int out_size) {
    const float* P;
    const int* occ;
    if (in_sizes[0] == DD * NPART) {
        P = (const float*)d_in[0];
        occ = (const int*)d_in[1];
    } else {
        P = (const float*)d_in[1];
        occ = (const int*)d_in[0];
    }
    float* out = (float*)d_out;

    const int smem = DD * PITCH * (int)sizeof(double);  // 74496 B
    cudaFuncSetAttribute(lu_probs_kernel,
                         cudaFuncAttributeMaxDynamicSharedMemorySize, smem);

    build_G_kernel<<<DD, DD>>>(P);
    lu_probs_kernel<<<NPART, 256, smem>>>(occ, out);
    prod_kernel<<<1, 32>>>(out);
}

// round 14
// speedup vs baseline: 1.6104x; 1.0299x over previous
#include <cuda_runtime.h>
#include <math.h>

#define DD 96
#define NPART 48
#define PITCH 97

__device__ double g_G[DD * DD];
__device__ double g_pk[NPART];
__device__ unsigned int g_count = 0;

// Fast fp64 reciprocal: f32 rcp seed + 2 fp64 Newton steps (~1e-14 rel).
__device__ __forceinline__ double fast_recip(double p) {
    float pf = (float)p;
    float rf;
    asm("rcp.approx.f32 %0, %1;" : "=f"(rf) : "f"(pf));
    double r = (double)rf;
    r = r * __fma_rn(-p, r, 2.0);
    r = r * __fma_rn(-p, r, 2.0);
    return r;
}

// ---------------------------------------------------------------------------
// G = I - P P^T  (96 blocks x 96 threads; measured-best variant).
// ---------------------------------------------------------------------------
__global__ void build_G_kernel(const float* __restrict__ P) {
    __shared__ float Pt[NPART][DD];  // Pt[t][i] = P[i*NPART+t]
    const int i = blockIdx.x;
    const int tid = threadIdx.x;  // 96

    for (int idx = tid; idx < DD * NPART; idx += DD) {
        int r = idx / NPART;
        int t = idx - r * NPART;
        Pt[t][r] = P[idx];
    }
    __syncthreads();

    const int j = tid;
    double a0 = 0.0, a1 = 0.0, a2 = 0.0, a3 = 0.0;
#pragma unroll
    for (int t = 0; t < NPART; t += 4) {
        a0 = __fma_rn((double)Pt[t][i],     (double)Pt[t][j],     a0);
        a1 = __fma_rn((double)Pt[t + 1][i], (double)Pt[t + 1][j], a1);
        a2 = __fma_rn((double)Pt[t + 2][i], (double)Pt[t + 2][j], a2);
        a3 = __fma_rn((double)Pt[t + 3][i], (double)Pt[t + 3][j], a3);
    }
    g_G[i * DD + j] = ((i == j) ? 1.0 : 0.0) - ((a0 + a1) + (a2 + a3));
}

// ---------------------------------------------------------------------------
// Per-k unpivoted symmetric elimination, RANK-2 steps: one barrier retires two
// pivots.  Warps 1..7: rank-2 trailing update of rows >= i0+4.  Warp 0:
// prepares the next pivot pair (rows i0+2, i0+3) -> publishes their fully
// updated rows + pivots + reciprocals for the next iteration.
// Factors come from pivot-row values (symmetry of the iterate).
// Ends with a fused "last block computes prob_sample" reduction.
// ---------------------------------------------------------------------------
__global__ void __launch_bounds__(256, 1)
lu_probs_kernel(const int* __restrict__ occ, float* __restrict__ out) {
    extern __shared__ double A_[];     // [DD][PITCH] dynamic
    __shared__ double U[2][2][DD];     // pair-buffered pivot rows
    __shared__ double s_inv[2][2];
    __shared__ double s_piv[DD];
    __shared__ double sc[2][DD];
    __shared__ int s_occ[NPART];
    __shared__ int s_last;

    const int k = blockIdx.x;
    const int m = DD - NPART + k + 1;   // 49 + k
    const int tid = threadIdx.x;        // 256
    const int tx = tid & 31;
    const int ty = tid >> 5;

    if (tid < NPART) s_occ[tid] = occ[tid];

    // Load leading m x m block of G.
    for (int r = ty; r < m; r += 8)
        for (int c = tx; c < m; c += 32)
            A_[r * PITCH + c] = g_G[r * DD + c];
    __syncthreads();
    if (tid < k) {                      // distinct positions -> race-free
        int p = s_occ[tid];
        if (p < m) A_[p * PITCH + p] -= 1.0;
    }
    __syncthreads();

    // Init: pivot rows 0 and 1.
    if (tid < m) U[0][0][tid] = A_[tid];
    if (tid == 0) {
        double p0 = A_[0];
        s_piv[0] = p0;
        s_inv[0][0] = fast_recip(p0);
    }
    __syncthreads();
    if (ty == 0) {
        const double inv0 = s_inv[0][0];
        const double* __restrict__ u0 = U[0][0];
        const double l1 = u0[1] * inv0;
        double pcap = 0.0;
        for (int c = 1 + tx; c < m; c += 32) {
            double v = __fma_rn(-l1, u0[c], A_[PITCH + c]);
            U[0][1][c] = v;
            if (c == 1) pcap = v;       // lane 0 only
        }
        if (tx == 0) {
            s_piv[1] = pcap;
            s_inv[0][1] = fast_recip(pcap);
        }
    }
    __syncthreads();

    for (int i0 = 0; i0 + 2 < m; i0 += 2) {
        const int pb = (i0 >> 1) & 1;
        const double inv0 = s_inv[pb][0];
        const double inv1 = s_inv[pb][1];
        const double* __restrict__ u0 = U[pb][0];
        const double* __restrict__ u1 = U[pb][1];
        double* __restrict__ v2 = U[pb ^ 1][0];
        double* __restrict__ v3 = U[pb ^ 1][1];
        const int r2 = i0 + 2, r3 = i0 + 3;

        if (ty == 0) {
            // Finalize pivot row r2 (rank-2 update), capture pivot.
            const double la = u0[r2] * inv0;
            const double lb = u1[r2] * inv1;
            const double* __restrict__ arow2 = &A_[r2 * PITCH];
            double pcap2 = 0.0;
            for (int c = r2 + tx; c < m; c += 32) {
                double v = arow2[c];
                v = __fma_rn(-la, u0[c], v);
                v = __fma_rn(-lb, u1[c], v);
                v2[c] = v;
                if (c == r2) pcap2 = v;
            }
            const double p2 = __shfl_sync(0xFFFFFFFFu, pcap2, 0);
            const double inv2 = fast_recip(p2);
            if (tx == 0) {
                s_piv[r2] = p2;
                s_inv[pb ^ 1][0] = inv2;
            }
            __syncwarp();
            if (r3 < m) {
                // Finalize pivot row r3: rank-2 + elimination vs row r2.
                const double lc = u0[r3] * inv0;
                const double ld = u1[r3] * inv1;
                const double f2 = v2[r3] * inv2;
                const double* __restrict__ arow3 = &A_[r3 * PITCH];
                double pcap3 = 0.0;
                for (int c = r3 + tx; c < m; c += 32) {
                    double v = arow3[c];
                    v = __fma_rn(-lc, u0[c], v);
                    v = __fma_rn(-ld, u1[c], v);
                    v = __fma_rn(-f2, v2[c], v);
                    v3[c] = v;
                    if (c == r3) pcap3 = v;
                }
                if (tx == 0) {
                    s_piv[r3] = pcap3;
                    s_inv[pb ^ 1][1] = fast_recip(pcap3);
                }
            }
        } else {
            // Rank-2 trailing update of rows i0+4 .. m-1 (stride 7).
            for (int r = i0 + 3 + ty; r < m; r += 7) {
                const double la = u0[r] * inv0;
                const double lb = u1[r] * inv1;
                double* __restrict__ arow = &A_[r * PITCH];
                for (int c = r2 + tx; c < m; c += 32) {
                    double v = arow[c];
                    v = __fma_rn(-la, u0[c], v);
                    v = __fma_rn(-lb, u1[c], v);
                    arow[c] = v;
                }
            }
        }
        __syncthreads();
    }

    const int xmin = (k == 0) ? 0 : s_occ[k - 1] + 1;

    // Inclusive prefix product of pivots masked to [xmin, m).
    if (tid < DD) sc[0][tid] = (tid >= xmin && tid < m) ? s_piv[tid] : 1.0;
    __syncthreads();
    int src = 0;
    for (int off = 1; off < DD; off <<= 1) {
        if (tid < DD) {
            double v = sc[src][tid];
            if (tid >= off) v *= sc[src][tid - off];
            sc[src ^ 1][tid] = v;
        }
        __syncthreads();
        src ^= 1;
    }

    if (tid < DD) {
        const int x = tid;
        double pr = 0.0;
        if (x >= xmin && x < m) {
            const double S = (x == xmin) ? 1.0 : sc[src][x - 1];
            pr = -S * (s_piv[x] - 1.0);
            if (!(fabs(pr) > 1e-15)) pr = 0.0;
        }
        out[k * DD + x] = (float)pr;
        if (x == s_occ[k]) g_pk[k] = pr;
    }

    // ---- fused prob_sample: last block to finish multiplies g_pk ----
    __syncthreads();
    if (tid == 0) {
        __threadfence();
        unsigned int n = atomicAdd(&g_count, 1u);
        s_last = (n == NPART - 1) ? 1 : 0;
    }
    __syncthreads();
    if (s_last) {
        if (tid < 32) {
            volatile double* vp = g_pk;
            double v = vp[tid];
            if (tid < 16) v *= vp[32 + tid];
#pragma unroll
            for (int off = 16; off > 0; off >>= 1)
                v *= __shfl_xor_sync(0xFFFFFFFFu, v, off);
            if (tid == 0) {
                out[NPART * DD] = (float)v;
                g_count = 0;  // reset for next graph replay
            }
        }
    }
}

extern "C" void kernel_launch(void* const* d_in, const int* in_sizes, int n_in,
                              void* d_out, int out_size) {
    const float* P;
    const int* occ;
    if (in_sizes[0] == DD * NPART) {
        P = (const float*)d_in[0];
        occ = (const int*)d_in[1];
    } else {
        P = (const float*)d_in[1];
        occ = (const int*)d_in[0];
    }
    float* out = (float*)d_out;

    const int smem = DD * PITCH * (int)sizeof(double);  // 74496 B
    cudaFuncSetAttribute(lu_probs_kernel,
                         cudaFuncAttributeMaxDynamicSharedMemorySize, smem);

    build_G_kernel<<<DD, DD>>>(P);
    lu_probs_kernel<<<NPART, 256, smem>>>(occ, out);
}